// round 1
// baseline (speedup 1.0000x reference)
#include <cuda_runtime.h>

// out[b, d] = initial[b, d] * (sum_k X[b,k]*alphas[k]) + X[b,d] + bias[d]
// B = 16384 rows, D = 2048 cols, fp32.
//
// One CTA per row. 256 threads x 2 float4 = 2048 elements.
// X is loaded once into registers, used for both the dot product and the
// epilogue. Block reduction via warp shuffle + shared memory.

#define THREADS 256
#define D_DIM 2048
#define VEC_PER_THREAD 2   // 2 float4 per thread: 256*2*4 = 2048

__global__ __launch_bounds__(THREADS, 8)
void crossnet_kernel(const float* __restrict__ initial,
                     const float* __restrict__ X,
                     const float* __restrict__ alphas,
                     const float* __restrict__ bias,
                     float* __restrict__ out)
{
    const int row = blockIdx.x;
    const int t = threadIdx.x;

    const float4* __restrict__ X4 = reinterpret_cast<const float4*>(X) + (size_t)row * (D_DIM / 4);
    const float4* __restrict__ I4 = reinterpret_cast<const float4*>(initial) + (size_t)row * (D_DIM / 4);
    const float4* __restrict__ A4 = reinterpret_cast<const float4*>(alphas);
    const float4* __restrict__ B4 = reinterpret_cast<const float4*>(bias);
    float4* __restrict__ O4 = reinterpret_cast<float4*>(out) + (size_t)row * (D_DIM / 4);

    // Front-batched loads: X (kept for epilogue) and alphas.
    float4 x0 = X4[t];
    float4 x1 = X4[t + THREADS];
    float4 a0 = A4[t];              // hot in L2/L1 across all rows
    float4 a1 = A4[t + THREADS];

    // Per-thread partial dot product.
    float dot = x0.x * a0.x + x0.y * a0.y + x0.z * a0.z + x0.w * a0.w
              + x1.x * a1.x + x1.y * a1.y + x1.z * a1.z + x1.w * a1.w;

    // Warp reduce.
    #pragma unroll
    for (int off = 16; off > 0; off >>= 1)
        dot += __shfl_xor_sync(0xFFFFFFFFu, dot, off);

    // Block reduce across 8 warps.
    __shared__ float warp_sums[THREADS / 32];
    __shared__ float scale_sh;
    const int lane = t & 31;
    const int wid = t >> 5;
    if (lane == 0) warp_sums[wid] = dot;
    __syncthreads();
    if (wid == 0) {
        float s = (lane < THREADS / 32) ? warp_sums[lane] : 0.0f;
        #pragma unroll
        for (int off = 4; off > 0; off >>= 1)
            s += __shfl_xor_sync(0xFFFFFFFFu, s, off);
        if (lane == 0) scale_sh = s;
    }

    // Load initial + bias while the reduction settles (independent of barrier
    // result, but placed after sync for smem correctness; the LDGs still
    // overlap the epilogue math via the scoreboard).
    float4 i0 = I4[t];
    float4 i1 = I4[t + THREADS];
    float4 b0 = B4[t];
    float4 b1 = B4[t + THREADS];

    __syncthreads();
    const float scale = scale_sh;

    float4 o0, o1;
    o0.x = fmaf(i0.x, scale, x0.x + b0.x);
    o0.y = fmaf(i0.y, scale, x0.y + b0.y);
    o0.z = fmaf(i0.z, scale, x0.z + b0.z);
    o0.w = fmaf(i0.w, scale, x0.w + b0.w);
    o1.x = fmaf(i1.x, scale, x1.x + b1.x);
    o1.y = fmaf(i1.y, scale, x1.y + b1.y);
    o1.z = fmaf(i1.z, scale, x1.z + b1.z);
    o1.w = fmaf(i1.w, scale, x1.w + b1.w);

    O4[t] = o0;
    O4[t + THREADS] = o1;
}

extern "C" void kernel_launch(void* const* d_in, const int* in_sizes, int n_in,
                              void* d_out, int out_size)
{
    const float* initial = (const float*)d_in[0];
    const float* X       = (const float*)d_in[1];
    const float* alphas  = (const float*)d_in[2];
    const float* bias    = (const float*)d_in[3];
    float* out           = (float*)d_out;

    const int B = in_sizes[0] / D_DIM;   // 16384
    crossnet_kernel<<<B, THREADS>>>(initial, X, alphas, bias, out);
}

// round 2
// speedup vs baseline: 1.0005x; 1.0005x over previous
#include <cuda_runtime.h>

// out[b, d] = initial[b, d] * (sum_k X[b,k]*alphas[k]) + X[b,d] + bias[d]
// B = 16384 rows, D = 2048 cols, fp32.
//
// One CTA per row. 256 threads x 2 float4 = 2048 elements.
// All global loads front-batched before the block reduction so the LSU/DRAM
// pipe stays busy across the barriers. Streaming cache hints on the
// single-use rows (X, initial) and the write-once output.

#define THREADS 256
#define D_DIM 2048

__global__ __launch_bounds__(THREADS, 8)
void crossnet_kernel(const float* __restrict__ initial,
                     const float* __restrict__ X,
                     const float* __restrict__ alphas,
                     const float* __restrict__ bias,
                     float* __restrict__ out)
{
    const int row = blockIdx.x;
    const int t = threadIdx.x;

    const float4* __restrict__ X4 = reinterpret_cast<const float4*>(X) + (size_t)row * (D_DIM / 4);
    const float4* __restrict__ I4 = reinterpret_cast<const float4*>(initial) + (size_t)row * (D_DIM / 4);
    const float4* __restrict__ A4 = reinterpret_cast<const float4*>(alphas);
    const float4* __restrict__ B4 = reinterpret_cast<const float4*>(bias);
    float4* __restrict__ O4 = reinterpret_cast<float4*>(out) + (size_t)row * (D_DIM / 4);

    // Front-batch ALL global loads (MLP_p1 = 8 streaming + 4 cached).
    // X / initial rows are single-use -> evict-first (.cs).
    float4 x0 = __ldcs(&X4[t]);
    float4 x1 = __ldcs(&X4[t + THREADS]);
    float4 i0 = __ldcs(&I4[t]);
    float4 i1 = __ldcs(&I4[t + THREADS]);
    float4 a0 = A4[t];              // reused by every CTA -> default caching
    float4 a1 = A4[t + THREADS];
    float4 b0 = B4[t];
    float4 b1 = B4[t + THREADS];

    // Per-thread partial dot product.
    float dot = x0.x * a0.x + x0.y * a0.y + x0.z * a0.z + x0.w * a0.w
              + x1.x * a1.x + x1.y * a1.y + x1.z * a1.z + x1.w * a1.w;

    // Warp reduce.
    #pragma unroll
    for (int off = 16; off > 0; off >>= 1)
        dot += __shfl_xor_sync(0xFFFFFFFFu, dot, off);

    // Block reduce across 8 warps.
    __shared__ float warp_sums[THREADS / 32];
    __shared__ float scale_sh;
    const int lane = t & 31;
    const int wid = t >> 5;
    if (lane == 0) warp_sums[wid] = dot;
    __syncthreads();
    if (wid == 0) {
        float s = (lane < THREADS / 32) ? warp_sums[lane] : 0.0f;
        #pragma unroll
        for (int off = 4; off > 0; off >>= 1)
            s += __shfl_xor_sync(0xFFFFFFFFu, s, off);
        if (lane == 0) scale_sh = s;
    }
    __syncthreads();
    const float scale = scale_sh;

    float4 o0, o1;
    o0.x = fmaf(i0.x, scale, x0.x + b0.x);
    o0.y = fmaf(i0.y, scale, x0.y + b0.y);
    o0.z = fmaf(i0.z, scale, x0.z + b0.z);
    o0.w = fmaf(i0.w, scale, x0.w + b0.w);
    o1.x = fmaf(i1.x, scale, x1.x + b1.x);
    o1.y = fmaf(i1.y, scale, x1.y + b1.y);
    o1.z = fmaf(i1.z, scale, x1.z + b1.z);
    o1.w = fmaf(i1.w, scale, x1.w + b1.w);

    // Output never re-read -> streaming store.
    __stcs(&O4[t], o0);
    __stcs(&O4[t + THREADS], o1);
}

extern "C" void kernel_launch(void* const* d_in, const int* in_sizes, int n_in,
                              void* d_out, int out_size)
{
    const float* initial = (const float*)d_in[0];
    const float* X       = (const float*)d_in[1];
    const float* alphas  = (const float*)d_in[2];
    const float* bias    = (const float*)d_in[3];
    float* out           = (float*)d_out;

    const int B = in_sizes[0] / D_DIM;   // 16384
    crossnet_kernel<<<B, THREADS>>>(initial, X, alphas, bias, out);
}